// round 6
// baseline (speedup 1.0000x reference)
#include <cuda_runtime.h>

// SSIM map: 3x3 mean filter (reflect pad 1) fused, fp32 in/out.
// f32x2-packed arithmetic (FFMA2/FADD2 via PTX) to halve FMA-pipe issue.
// Shapes fixed: planes = N*C = 96, H=384, W=640.

#define HH 384
#define WW 640
#define STRIP 8          // output rows per thread
#define TPB 160          // 160 threads * 4 cols = 640 = full width

typedef unsigned long long u64;

__device__ __forceinline__ u64 pack2(float lo, float hi) {
    u64 r; asm("mov.b64 %0, {%1, %2};" : "=l"(r) : "f"(lo), "f"(hi)); return r;
}
__device__ __forceinline__ void unpack2(u64 v, float& lo, float& hi) {
    asm("mov.b64 {%0, %1}, %2;" : "=f"(lo), "=f"(hi) : "l"(v));
}
__device__ __forceinline__ u64 add2(u64 a, u64 b) {
    u64 r; asm("add.rn.f32x2 %0, %1, %2;" : "=l"(r) : "l"(a), "l"(b)); return r;
}
__device__ __forceinline__ u64 mul2(u64 a, u64 b) {
    u64 r; asm("mul.rn.f32x2 %0, %1, %2;" : "=l"(r) : "l"(a), "l"(b)); return r;
}
__device__ __forceinline__ u64 fma2(u64 a, u64 b, u64 c) {
    u64 r; asm("fma.rn.f32x2 %0, %1, %2, %3;" : "=l"(r) : "l"(a), "l"(b), "l"(c)); return r;
}
__device__ __forceinline__ u64 neg2(u64 a) {   // lane-wise negate: sign-bit xor (ALU pipe)
    return a ^ 0x8000000080000000ULL;
}

__device__ __forceinline__ int rrow(int r) {
    // reflect index for pad=1: -1 -> 1, H -> H-2
    return r < 0 ? -r : (r >= HH ? 2 * HH - 2 - r : r);
}

// Load 6 columns (c0-1 .. c0+4) of one row, packed into 3 f32x2 pairs:
// q[0]=(c-1,c0) q[1]=(c1,c2) q[2]=(c3,c4)
__device__ __forceinline__ void load_row6p(const float* __restrict__ base,
                                           int c0, int cm1, int cp4, u64 q[3]) {
    float4 v = *(const float4*)(base + c0);
    float a = __ldg(base + cm1);
    float b = __ldg(base + cp4);
    q[0] = pack2(a, v.x);
    q[1] = pack2(v.y, v.z);
    q[2] = pack2(v.w, b);
}

// Horizontal 3-tap sums: lanes s0..s5 in p0,p1,p2 -> S01=(S0,S1), S23=(S2,S3)
// (S0,S1) = (s0,s1)+(s1,s2)+(s2,s3);  (S2,S3) = (s2,s3)+(s3,s4)+(s4,s5)
__device__ __forceinline__ void h3(u64 p0, u64 p1, u64 p2, u64& S01, u64& S23) {
    float l0, h0, l1, h1, l2, h2;
    unpack2(p0, l0, h0); unpack2(p1, l1, h1); unpack2(p2, l2, h2);
    u64 shA = pack2(h0, l1);   // (s1,s2)
    u64 shB = pack2(h1, l2);   // (s3,s4)
    S01 = add2(add2(p0, shA), p1);
    S23 = add2(add2(p1, shB), p2);
}

// SSIM for one packed pair of outputs.
__device__ __forceinline__ void ssim2(u64 Sx, u64 Sy, u64 Sxx, u64 Syy, u64 Sxy,
                                      u64 inv9_2, u64 two2, u64 c1_2, u64 c2_2,
                                      float& r0, float& r1) {
    u64 mux = mul2(Sx, inv9_2);
    u64 muy = mul2(Sy, inv9_2);
    u64 mxx = mul2(mux, mux);
    u64 myy = mul2(muy, muy);
    u64 mxy = mul2(mux, muy);
    u64 varx = fma2(Sxx, inv9_2, neg2(mxx));
    u64 vary = fma2(Syy, inv9_2, neg2(myy));
    u64 cov  = fma2(Sxy, inv9_2, neg2(mxy));
    u64 num = mul2(fma2(two2, mxy, c1_2), fma2(two2, cov, c2_2));
    u64 den = mul2(add2(add2(mxx, myy), c1_2), add2(add2(varx, vary), c2_2));
    float n0, n1, d0, d1;
    unpack2(num, n0, n1); unpack2(den, d0, d1);
    r0 = fminf(fmaxf(__fdividef(n0, d0), 0.0f), 1.0f);   // FMNMX -> ALU pipe
    r1 = fminf(fmaxf(__fdividef(n1, d1), 0.0f), 1.0f);
}

__global__ __launch_bounds__(TPB)
void ssim_kernel(const float* __restrict__ x,
                 const float* __restrict__ y,
                 float* __restrict__ out)
{
    const int tx    = threadIdx.x;
    const int c0    = tx * 4;
    const int plane = blockIdx.y;
    const int r0    = blockIdx.x * STRIP;

    const size_t pbase = (size_t)plane * HH * WW;
    const float* xp = x + pbase;
    const float* yp = y + pbase;
    float* op       = out + pbase;

    const int cm1 = (c0 == 0) ? 1 : c0 - 1;
    const int cp4 = (c0 + 4 >= WW) ? (WW - 2) : (c0 + 4);

    // Packed constants (lane-replicated).
    const u64 inv9_2 = pack2(1.0f / 9.0f, 1.0f / 9.0f);
    const u64 two2   = pack2(2.0f, 2.0f);
    const u64 c1_2   = pack2(1.0e-4f, 1.0e-4f);
    const u64 c2_2   = pack2(9.0e-4f, 9.0e-4f);

    // 3-row rotating packed buffers: 3 pairs per row per input.
    u64 xq[3][3], yq[3][3];

    #pragma unroll
    for (int k = 0; k < 2; k++) {
        const int r = rrow(r0 - 1 + k);
        load_row6p(xp + (size_t)r * WW, c0, cm1, cp4, xq[k]);
        load_row6p(yp + (size_t)r * WW, c0, cm1, cp4, yq[k]);
    }

    #pragma unroll
    for (int i = 0; i < STRIP; i++) {
        {
            const int slot = (i + 2) % 3;
            const int r = rrow(r0 + i + 1);
            load_row6p(xp + (size_t)r * WW, c0, cm1, cp4, xq[slot]);
            load_row6p(yp + (size_t)r * WW, c0, cm1, cp4, yq[slot]);
        }

        const int s0 = i % 3, s1 = (i + 1) % 3, s2 = (i + 2) % 3;

        // Vertical (column) sums, packed over 3 column-pairs.
        u64 sx[3], sy[3], sxx[3], syy[3], sxy[3];
        #pragma unroll
        for (int k = 0; k < 3; k++) {
            const u64 a0 = xq[s0][k], a1 = xq[s1][k], a2 = xq[s2][k];
            const u64 b0 = yq[s0][k], b1 = yq[s1][k], b2 = yq[s2][k];
            sx[k]  = add2(add2(a0, a1), a2);
            sy[k]  = add2(add2(b0, b1), b2);
            sxx[k] = fma2(a0, a0, fma2(a1, a1, mul2(a2, a2)));
            syy[k] = fma2(b0, b0, fma2(b1, b1, mul2(b2, b2)));
            sxy[k] = fma2(a0, b0, fma2(a1, b1, mul2(a2, b2)));
        }

        // Horizontal 3-sums -> packed output pairs (0,1) and (2,3).
        u64 Sx01, Sx23, Sy01, Sy23, Sxx01, Sxx23, Syy01, Syy23, Sxy01, Sxy23;
        h3(sx[0],  sx[1],  sx[2],  Sx01,  Sx23);
        h3(sy[0],  sy[1],  sy[2],  Sy01,  Sy23);
        h3(sxx[0], sxx[1], sxx[2], Sxx01, Sxx23);
        h3(syy[0], syy[1], syy[2], Syy01, Syy23);
        h3(sxy[0], sxy[1], sxy[2], Sxy01, Sxy23);

        float r0v, r1v, r2v, r3v;
        ssim2(Sx01, Sy01, Sxx01, Syy01, Sxy01, inv9_2, two2, c1_2, c2_2, r0v, r1v);
        ssim2(Sx23, Sy23, Sxx23, Syy23, Sxy23, inv9_2, two2, c1_2, c2_2, r2v, r3v);

        float4 res = make_float4(r0v, r1v, r2v, r3v);
        *(float4*)(op + (size_t)(r0 + i) * WW + c0) = res;
    }
}

extern "C" void kernel_launch(void* const* d_in, const int* in_sizes, int n_in,
                              void* d_out, int out_size) {
    const float* x = (const float*)d_in[0];
    const float* y = (const float*)d_in[1];
    float* out = (float*)d_out;

    const int planes = in_sizes[0] / (HH * WW);   // 96
    dim3 grid(HH / STRIP, planes);                // (48, 96)
    ssim_kernel<<<grid, TPB>>>(x, y, out);
}

// round 7
// speedup vs baseline: 1.2699x; 1.2699x over previous
#include <cuda_runtime.h>

// SSIM map: 3x3 mean filter (reflect pad 1) fused, fp32 in/out.
// Hybrid: f32x2 packed VERTICAL sums (naturally pair-aligned from float4 loads,
// unpack-only consumption), scalar horizontal with shared sub-sums, and
// rescaled SSIM algebra (x81^2) to eliminate all /9 scaling.
// Shapes fixed: planes = N*C = 96, H=384, W=640.

#define HH 384
#define WW 640
#define STRIP 8          // output rows per thread
#define TPB 160          // 160 threads * 4 cols = 640 = full width

typedef unsigned long long u64;

__device__ __forceinline__ u64 pack2(float lo, float hi) {
    u64 r; asm("mov.b64 %0, {%1, %2};" : "=l"(r) : "f"(lo), "f"(hi)); return r;
}
__device__ __forceinline__ void unpack2(u64 v, float& lo, float& hi) {
    asm("mov.b64 {%0, %1}, %2;" : "=f"(lo), "=f"(hi) : "l"(v));
}
__device__ __forceinline__ u64 add2(u64 a, u64 b) {
    u64 r; asm("add.rn.f32x2 %0, %1, %2;" : "=l"(r) : "l"(a), "l"(b)); return r;
}
__device__ __forceinline__ u64 mul2(u64 a, u64 b) {
    u64 r; asm("mul.rn.f32x2 %0, %1, %2;" : "=l"(r) : "l"(a), "l"(b)); return r;
}
__device__ __forceinline__ u64 fma2(u64 a, u64 b, u64 c) {
    u64 r; asm("fma.rn.f32x2 %0, %1, %2, %3;" : "=l"(r) : "l"(a), "l"(b), "l"(c)); return r;
}

__device__ __forceinline__ int rrow(int r) {
    // reflect index for pad=1: -1 -> 1, H -> H-2
    return r < 0 ? -r : (r >= HH ? 2 * HH - 2 - r : r);
}

__global__ __launch_bounds__(TPB)
void ssim_kernel(const float* __restrict__ x,
                 const float* __restrict__ y,
                 float* __restrict__ out)
{
    const int tx    = threadIdx.x;
    const int c0    = tx * 4;
    const int plane = blockIdx.y;
    const int r0    = blockIdx.x * STRIP;

    const size_t pbase = (size_t)plane * HH * WW;
    const float* xp = x + pbase;
    const float* yp = y + pbase;
    float* op       = out + pbase;

    const int cm1 = (c0 == 0) ? 1 : c0 - 1;
    const int cp4 = (c0 + 4 >= WW) ? (WW - 2) : (c0 + 4);

    // Rescaled constants: 81*C1, 81*C2 (num and den both scaled by 81^2 -> cancels).
    const float C1S = 81.0f * 1.0e-4f;
    const float C2S = 81.0f * 9.0e-4f;

    // 3-row rotating buffers: edge scalars + 2 naturally-aligned packed pairs, per input.
    float xe0[3], xe5[3], ye0[3], ye5[3];
    u64 xp01[3], xp23[3], yp01[3], yp23[3];

    #pragma unroll
    for (int k = 0; k < 2; k++) {
        const int r = rrow(r0 - 1 + k);
        const float* xb = xp + (size_t)r * WW;
        const float* yb = yp + (size_t)r * WW;
        float4 v = *(const float4*)(xb + c0);
        xe0[k] = __ldg(xb + cm1); xe5[k] = __ldg(xb + cp4);
        xp01[k] = pack2(v.x, v.y); xp23[k] = pack2(v.z, v.w);
        float4 w = *(const float4*)(yb + c0);
        ye0[k] = __ldg(yb + cm1); ye5[k] = __ldg(yb + cp4);
        yp01[k] = pack2(w.x, w.y); yp23[k] = pack2(w.z, w.w);
    }

    #pragma unroll
    for (int i = 0; i < STRIP; i++) {
        {
            const int slot = (i + 2) % 3;
            const int r = rrow(r0 + i + 1);
            const float* xb = xp + (size_t)r * WW;
            const float* yb = yp + (size_t)r * WW;
            float4 v = *(const float4*)(xb + c0);
            xe0[slot] = __ldg(xb + cm1); xe5[slot] = __ldg(xb + cp4);
            xp01[slot] = pack2(v.x, v.y); xp23[slot] = pack2(v.z, v.w);
            float4 w = *(const float4*)(yb + c0);
            ye0[slot] = __ldg(yb + cm1); ye5[slot] = __ldg(yb + cp4);
            yp01[slot] = pack2(w.x, w.y); yp23[slot] = pack2(w.z, w.w);
        }

        const int s0 = i % 3, s1 = (i + 1) % 3, s2 = (i + 2) % 3;

        // ---- Vertical sums: packed for the 4 interior columns ----
        const u64 a0 = xp01[s0], a1 = xp01[s1], a2 = xp01[s2];
        const u64 a3 = xp23[s0], a4 = xp23[s1], a5 = xp23[s2];
        const u64 b0 = yp01[s0], b1 = yp01[s1], b2 = yp01[s2];
        const u64 b3 = yp23[s0], b4 = yp23[s1], b5 = yp23[s2];

        const u64 SX01  = add2(add2(a0, a1), a2);
        const u64 SX23  = add2(add2(a3, a4), a5);
        const u64 SY01  = add2(add2(b0, b1), b2);
        const u64 SY23  = add2(add2(b3, b4), b5);
        const u64 SXX01 = fma2(a0, a0, fma2(a1, a1, mul2(a2, a2)));
        const u64 SXX23 = fma2(a3, a3, fma2(a4, a4, mul2(a5, a5)));
        const u64 SYY01 = fma2(b0, b0, fma2(b1, b1, mul2(b2, b2)));
        const u64 SYY23 = fma2(b3, b3, fma2(b4, b4, mul2(b5, b5)));
        const u64 SXY01 = fma2(a0, b0, fma2(a1, b1, mul2(a2, b2)));
        const u64 SXY23 = fma2(a3, b3, fma2(a4, b4, mul2(a5, b5)));

        // ---- Vertical sums: scalar for the 2 edge columns ----
        const float ex0 = xe0[s0], ex1 = xe0[s1], ex2 = xe0[s2];
        const float fx0 = xe5[s0], fx1 = xe5[s1], fx2 = xe5[s2];
        const float ey0 = ye0[s0], ey1 = ye0[s1], ey2 = ye0[s2];
        const float fy0 = ye5[s0], fy1 = ye5[s1], fy2 = ye5[s2];

        const float sxL  = ex0 + ex1 + ex2;
        const float syL  = ey0 + ey1 + ey2;
        const float sxxL = fmaf(ex0, ex0, fmaf(ex1, ex1, ex2 * ex2));
        const float syyL = fmaf(ey0, ey0, fmaf(ey1, ey1, ey2 * ey2));
        const float sxyL = fmaf(ex0, ey0, fmaf(ex1, ey1, ex2 * ey2));
        const float sxR  = fx0 + fx1 + fx2;
        const float syR  = fy0 + fy1 + fy2;
        const float sxxR = fmaf(fx0, fx0, fmaf(fx1, fx1, fx2 * fx2));
        const float syyR = fmaf(fy0, fy0, fmaf(fy1, fy1, fy2 * fy2));
        const float sxyR = fmaf(fx0, fy0, fmaf(fx1, fy1, fx2 * fy2));

        // ---- Unpack (free: register aliasing) ----
        float sx0, sx1, sx2c, sx3, sy0, sy1, sy2c, sy3;
        float sxx0, sxx1, sxx2c, sxx3, syy0, syy1, syy2c, syy3, sxy0, sxy1, sxy2c, sxy3;
        unpack2(SX01, sx0, sx1);   unpack2(SX23, sx2c, sx3);
        unpack2(SY01, sy0, sy1);   unpack2(SY23, sy2c, sy3);
        unpack2(SXX01, sxx0, sxx1); unpack2(SXX23, sxx2c, sxx3);
        unpack2(SYY01, syy0, syy1); unpack2(SYY23, syy2c, syy3);
        unpack2(SXY01, sxy0, sxy1); unpack2(SXY23, sxy2c, sxy3);

        // ---- Horizontal 3-sums via shared sub-sums: 6 adds per stat ----
        float Sx[4], Sy[4], Sxx[4], Syy[4], Sxy[4];
        {
            float u, v;
            u = sx0 + sx1;   v = sx2c + sx3;
            Sx[0] = sxL + u;  Sx[1] = u + sx2c;  Sx[2] = sx1 + v;  Sx[3] = v + sxR;
            u = sy0 + sy1;   v = sy2c + sy3;
            Sy[0] = syL + u;  Sy[1] = u + sy2c;  Sy[2] = sy1 + v;  Sy[3] = v + syR;
            u = sxx0 + sxx1; v = sxx2c + sxx3;
            Sxx[0] = sxxL + u; Sxx[1] = u + sxx2c; Sxx[2] = sxx1 + v; Sxx[3] = v + sxxR;
            u = syy0 + syy1; v = syy2c + syy3;
            Syy[0] = syyL + u; Syy[1] = u + syy2c; Syy[2] = syy1 + v; Syy[3] = v + syyR;
            u = sxy0 + sxy1; v = sxy2c + sxy3;
            Sxy[0] = sxyL + u; Sxy[1] = u + sxy2c; Sxy[2] = sxy1 + v; Sxy[3] = v + sxyR;
        }

        // ---- SSIM, rescaled by 81^2 (cancels in the ratio) ----
        float resv[4];
        #pragma unroll
        for (int o = 0; o < 4; o++) {
            const float P  = Sx[o] * Sy[o];
            const float Qx = Sx[o] * Sx[o];
            const float Qy = Sy[o] * Sy[o];
            const float A  = fmaf(Sxx[o], 9.0f, -Qx);   // 9*Sxx - Sx^2  (FFMA-imm)
            const float B  = fmaf(Syy[o], 9.0f, -Qy);
            const float Cc = fmaf(Sxy[o], 9.0f, -P);
            const float num = fmaf(P, 2.0f, C1S) * fmaf(Cc, 2.0f, C2S);
            const float den = (Qx + Qy + C1S) * (A + B + C2S);
            float s = __fdividef(num, den);
            resv[o] = fminf(fmaxf(s, 0.0f), 1.0f);
        }

        float4 res = make_float4(resv[0], resv[1], resv[2], resv[3]);
        *(float4*)(op + (size_t)(r0 + i) * WW + c0) = res;
    }
}

extern "C" void kernel_launch(void* const* d_in, const int* in_sizes, int n_in,
                              void* d_out, int out_size) {
    const float* x = (const float*)d_in[0];
    const float* y = (const float*)d_in[1];
    float* out = (float*)d_out;

    const int planes = in_sizes[0] / (HH * WW);   // 96
    dim3 grid(HH / STRIP, planes);                // (48, 96)
    ssim_kernel<<<grid, TPB>>>(x, y, out);
}